// round 3
// baseline (speedup 1.0000x reference)
#include <cuda_runtime.h>
#include <math.h>

#define N_NODES 8192
#define E_EDGES 262144
#define E_TOT   (E_EDGES + N_NODES)   // 270336, with self loops
#define IN_CH   256
#define HEADS   8
#define CPH     32
#define HC      256                    // HEADS*CPH
#define VLEN    (N_NODES * HC)         // 2097152
#define NEG_SLOPE 0.2f

// ---------------- device scratch (no allocations allowed) ----------------
__device__ float g_xh[N_NODES * HC];        // projected features [n, h*c]
__device__ float g_asrc[N_NODES * HEADS];
__device__ float g_adst[N_NODES * HEADS];
__device__ int   g_deg[N_NODES];
__device__ int   g_fill[N_NODES];
__device__ int   g_rowptr[N_NODES + 1];
__device__ int   g_csrc[E_TOT];
__device__ float g_v[VLEN];                 // agg + bias, flattened
__device__ float g_y[CPH];                  // partial output logits

// ---------------- K0: zero scratch ----------------
__global__ void k_zero() {
    int i = blockIdx.x * blockDim.x + threadIdx.x;
    if (i < N_NODES) { g_deg[i] = 0; g_fill[i] = 0; }
    if (i < CPH) g_y[i] = 0.f;
}

// ---------------- K1: GEMM xh = x @ lin_w^T ----------------
// x [N, 256] row-major, lin_w [256, 256] row-major (both K-major) -> A*B^T
// 64x64 tile, BK=16, 256 threads, 4x4 per thread
__global__ __launch_bounds__(256) void k_gemm(const float* __restrict__ x,
                                              const float* __restrict__ w) {
    __shared__ float As[64 * 17];
    __shared__ float Bs[64 * 17];
    int tid = threadIdx.x;
    int tx = tid & 15, ty = tid >> 4;
    int m0 = blockIdx.x * 64;
    int n0 = blockIdx.y * 64;

    float acc[4][4];
#pragma unroll
    for (int i = 0; i < 4; i++)
#pragma unroll
        for (int j = 0; j < 4; j++) acc[i][j] = 0.f;

    int lrow = tid >> 2;            // 0..63
    int lcol = (tid & 3) * 4;       // 0,4,8,12

    for (int k0 = 0; k0 < IN_CH; k0 += 16) {
        float4 av = *(const float4*)&x[(size_t)(m0 + lrow) * IN_CH + k0 + lcol];
        float4 bv = *(const float4*)&w[(size_t)(n0 + lrow) * IN_CH + k0 + lcol];
        As[lrow * 17 + lcol + 0] = av.x; As[lrow * 17 + lcol + 1] = av.y;
        As[lrow * 17 + lcol + 2] = av.z; As[lrow * 17 + lcol + 3] = av.w;
        Bs[lrow * 17 + lcol + 0] = bv.x; Bs[lrow * 17 + lcol + 1] = bv.y;
        Bs[lrow * 17 + lcol + 2] = bv.z; Bs[lrow * 17 + lcol + 3] = bv.w;
        __syncthreads();
#pragma unroll
        for (int k = 0; k < 16; k++) {
            float a[4], b[4];
#pragma unroll
            for (int i = 0; i < 4; i++) a[i] = As[(ty * 4 + i) * 17 + k];
#pragma unroll
            for (int j = 0; j < 4; j++) b[j] = Bs[(tx * 4 + j) * 17 + k];
#pragma unroll
            for (int i = 0; i < 4; i++)
#pragma unroll
                for (int j = 0; j < 4; j++) acc[i][j] = fmaf(a[i], b[j], acc[i][j]);
        }
        __syncthreads();
    }
#pragma unroll
    for (int i = 0; i < 4; i++)
#pragma unroll
        for (int j = 0; j < 4; j++)
            g_xh[(size_t)(m0 + ty * 4 + i) * HC + n0 + tx * 4 + j] = acc[i][j];
}

// ---------------- K2: per-node attention scalars ----------------
// warp per (node, head): a_src[n,h] = dot(xh[n,h,:], att_src[h,:])
__global__ __launch_bounds__(256) void k_attvec(const float* __restrict__ att_src,
                                                const float* __restrict__ att_dst) {
    int n = blockIdx.x;
    int h = threadIdx.x >> 5;
    int c = threadIdx.x & 31;
    float v = g_xh[(size_t)n * HC + h * CPH + c];
    float s1 = v * att_src[h * CPH + c];
    float s2 = v * att_dst[h * CPH + c];
#pragma unroll
    for (int off = 16; off; off >>= 1) {
        s1 += __shfl_down_sync(0xffffffffu, s1, off);
        s2 += __shfl_down_sync(0xffffffffu, s2, off);
    }
    if (c == 0) { g_asrc[n * HEADS + h] = s1; g_adst[n * HEADS + h] = s2; }
}

// ---------------- K3a: degree histogram over dst ----------------
__global__ void k_degree(const int* __restrict__ ei) {
    int e = blockIdx.x * blockDim.x + threadIdx.x;
    if (e >= E_TOT) return;
    int dst = (e < E_EDGES) ? ei[E_EDGES + e] : (e - E_EDGES);
    atomicAdd(&g_deg[dst], 1);
}

// ---------------- K3b: exclusive scan (single block, 1024 thr x 8) ----------------
__global__ __launch_bounds__(1024) void k_scan() {
    __shared__ int sh[1024];
    int t = threadIdx.x;
    int loc[8];
    int s = 0;
#pragma unroll
    for (int i = 0; i < 8; i++) { loc[i] = s; s += g_deg[t * 8 + i]; }
    sh[t] = s;
    __syncthreads();
    for (int off = 1; off < 1024; off <<= 1) {
        int v = (t >= off) ? sh[t - off] : 0;
        __syncthreads();
        sh[t] += v;
        __syncthreads();
    }
    int base = (t == 0) ? 0 : sh[t - 1];
#pragma unroll
    for (int i = 0; i < 8; i++) g_rowptr[t * 8 + i] = base + loc[i];
    if (t == 1023) g_rowptr[N_NODES] = sh[1023];
}

// ---------------- K3c: scatter src ids into CSR ----------------
__global__ void k_scatter(const int* __restrict__ ei) {
    int e = blockIdx.x * blockDim.x + threadIdx.x;
    if (e >= E_TOT) return;
    int src, dst;
    if (e < E_EDGES) { src = ei[e]; dst = ei[E_EDGES + e]; }
    else { src = e - E_EDGES; dst = src; }
    int pos = g_rowptr[dst] + atomicAdd(&g_fill[dst], 1);
    g_csrc[pos] = src;
}

// ---------------- K4: per-dst softmax + weighted aggregation ----------------
// one block (256 thr) per destination node
__global__ __launch_bounds__(256) void k_agg(const float* __restrict__ bias) {
    int i = blockIdx.x;
    int beg = g_rowptr[i], end = g_rowptr[i + 1];
    int tid = threadIdx.x;
    int lane = tid & 31, wid = tid >> 5;

    __shared__ float s_adst[HEADS];
    if (tid < HEADS) s_adst[tid] = g_adst[i * HEADS + tid];
    __syncthreads();

    // pass 1: online softmax stats per head
    float m[HEADS], s[HEADS];
#pragma unroll
    for (int h = 0; h < HEADS; h++) { m[h] = -1e30f; s[h] = 0.f; }
    for (int e = beg + tid; e < end; e += 256) {
        int j = g_csrc[e];
#pragma unroll
        for (int h = 0; h < HEADS; h++) {
            float v = g_asrc[j * HEADS + h] + s_adst[h];
            v = v > 0.f ? v : NEG_SLOPE * v;
            if (v > m[h]) { s[h] = s[h] * expf(m[h] - v) + 1.f; m[h] = v; }
            else s[h] += expf(v - m[h]);
        }
    }
    // warp reduce (m,s) pairs
#pragma unroll
    for (int h = 0; h < HEADS; h++) {
#pragma unroll
        for (int off = 16; off; off >>= 1) {
            float om = __shfl_down_sync(0xffffffffu, m[h], off);
            float os = __shfl_down_sync(0xffffffffu, s[h], off);
            float nm = fmaxf(m[h], om);
            s[h] = s[h] * expf(m[h] - nm) + os * expf(om - nm);
            m[h] = nm;
        }
    }
    __shared__ float rm[8][HEADS], rs[8][HEADS];
    if (lane == 0) {
#pragma unroll
        for (int h = 0; h < HEADS; h++) { rm[wid][h] = m[h]; rs[wid][h] = s[h]; }
    }
    __syncthreads();
    __shared__ float s_m[HEADS], s_dinv[HEADS];
    if (tid < HEADS) {
        int h = tid;
        float mm = rm[0][h], ss = rs[0][h];
#pragma unroll
        for (int w = 1; w < 8; w++) {
            float nm = fmaxf(mm, rm[w][h]);
            ss = ss * expf(mm - nm) + rs[w][h] * expf(rm[w][h] - nm);
            mm = nm;
        }
        s_m[h] = mm;
        s_dinv[h] = 1.f / ss;
    }

    // pass 2: weighted gather-accumulate; thread owns channel hc = tid
    __shared__ float s_alpha[32][HEADS];
    __shared__ int s_j[32];
    int h = tid >> 5;  // head of my channel
    float acc = 0.f;
    for (int base = beg; base < end; base += 32) {
        int nn = min(32, end - base);
        __syncthreads();   // protects s_m/s_dinv first iter, s_alpha/s_j reuse after
        if (tid < nn) {
            int j = g_csrc[base + tid];
            s_j[tid] = j;
#pragma unroll
            for (int h2 = 0; h2 < HEADS; h2++) {
                float v = g_asrc[j * HEADS + h2] + s_adst[h2];
                v = v > 0.f ? v : NEG_SLOPE * v;
                s_alpha[tid][h2] = expf(v - s_m[h2]) * s_dinv[h2];
            }
        }
        __syncthreads();
        for (int e = 0; e < nn; e++) {
            acc = fmaf(s_alpha[e][h], g_xh[(size_t)s_j[e] * HC + tid], acc);
        }
    }
    g_v[(size_t)i * HC + tid] = acc + bias[tid];
}

// ---------------- K5: y[c] = sum_k v[k] * out_w[c,k] ----------------
#define CHUNK 4096
__global__ __launch_bounds__(256) void k_matvec(const float* __restrict__ out_w) {
    __shared__ float sv[CHUNK];
    __shared__ float red[8];
    int k0 = blockIdx.x * CHUNK;
    int tid = threadIdx.x;
    const float4* v4 = (const float4*)&g_v[k0];
    float4* sv4 = (float4*)sv;
    for (int i = tid; i < CHUNK / 4; i += 256) sv4[i] = v4[i];
    __syncthreads();
    int lane = tid & 31, wid = tid >> 5;
    for (int c = 0; c < CPH; c++) {
        const float4* w4 = (const float4*)(out_w + (size_t)c * VLEN + k0);
        float p = 0.f;
        for (int i = tid; i < CHUNK / 4; i += 256) {
            float4 wv = w4[i];
            float4 vv = sv4[i];
            p = fmaf(wv.x, vv.x, p);
            p = fmaf(wv.y, vv.y, p);
            p = fmaf(wv.z, vv.z, p);
            p = fmaf(wv.w, vv.w, p);
        }
#pragma unroll
        for (int off = 16; off; off >>= 1) p += __shfl_down_sync(0xffffffffu, p, off);
        if (lane == 0) red[wid] = p;
        __syncthreads();
        if (tid == 0) {
            float t = 0.f;
#pragma unroll
            for (int w = 0; w < 8; w++) t += red[w];
            atomicAdd(&g_y[c], t);
        }
        __syncthreads();
    }
}

// ---------------- K6: softmax over 32 logits ----------------
__global__ void k_softmax(const float* __restrict__ out_b, float* __restrict__ out) {
    int t = threadIdx.x;  // 32 threads
    float v = g_y[t] + out_b[t];
    float mx = v;
#pragma unroll
    for (int off = 16; off; off >>= 1) mx = fmaxf(mx, __shfl_xor_sync(0xffffffffu, mx, off));
    float e = expf(v - mx);
    float ssum = e;
#pragma unroll
    for (int off = 16; off; off >>= 1) ssum += __shfl_xor_sync(0xffffffffu, ssum, off);
    out[t] = e / ssum;
}

// ---------------- launch ----------------
extern "C" void kernel_launch(void* const* d_in, const int* in_sizes, int n_in,
                              void* d_out, int out_size) {
    const float* x       = (const float*)d_in[0];
    const int*   ei      = (const int*)d_in[1];
    const float* lin_w   = (const float*)d_in[2];
    const float* att_src = (const float*)d_in[3];
    const float* att_dst = (const float*)d_in[4];
    const float* bias    = (const float*)d_in[5];
    const float* out_w   = (const float*)d_in[6];
    const float* out_b   = (const float*)d_in[7];
    float* out = (float*)d_out;

    k_zero<<<(N_NODES + 255) / 256, 256>>>();
    k_gemm<<<dim3(N_NODES / 64, HC / 64), 256>>>(x, lin_w);
    k_attvec<<<N_NODES, 256>>>(att_src, att_dst);
    k_degree<<<(E_TOT + 255) / 256, 256>>>(ei);
    k_scan<<<1, 1024>>>();
    k_scatter<<<(E_TOT + 255) / 256, 256>>>(ei);
    k_agg<<<N_NODES, 256>>>(bias);
    k_matvec<<<VLEN / CHUNK, 256>>>(out_w);
    k_softmax<<<1, 32>>>(out_b, out);
}

// round 4
// speedup vs baseline: 1.5416x; 1.5416x over previous
#include <cuda_runtime.h>
#include <math.h>

#define N_NODES 8192
#define E_EDGES 262144
#define E_TOT   (E_EDGES + N_NODES)   // 270336, with self loops
#define IN_CH   256
#define HEADS   8
#define CPH     32
#define HC      256                    // HEADS*CPH
#define VLEN    (N_NODES * HC)         // 2097152
#define NEG_SLOPE 0.2f

// ---------------- device scratch (no allocations allowed) ----------------
__device__ float g_xh[N_NODES * HC];        // projected features [n, h*c]
__device__ float g_asrc[N_NODES * HEADS];
__device__ float g_adst[N_NODES * HEADS];
__device__ int   g_deg[N_NODES];
__device__ int   g_fill[N_NODES];
__device__ int   g_rowptr[N_NODES + 1];
__device__ int   g_csrc[E_TOT];
__device__ float g_v[VLEN];                 // agg + bias, flattened
__device__ float g_y[CPH];                  // partial output logits

// ---------------- packed f32x2 helpers (Blackwell FFMA2) ----------------
__device__ __forceinline__ unsigned long long pk2(float lo, float hi) {
    unsigned long long r;
    asm("mov.b64 %0, {%1, %2};" : "=l"(r) : "f"(lo), "f"(hi));
    return r;
}
__device__ __forceinline__ void upk2(unsigned long long v, float& lo, float& hi) {
    asm("mov.b64 {%0, %1}, %2;" : "=f"(lo), "=f"(hi) : "l"(v));
}
__device__ __forceinline__ void fma2(unsigned long long& d,
                                     unsigned long long a, unsigned long long b) {
    asm("fma.rn.f32x2 %0, %1, %2, %3;" : "=l"(d) : "l"(a), "l"(b), "l"(d));
}

// ---------------- K0: init scratch ----------------
__global__ void k_zero() {
    int i = blockIdx.x * blockDim.x + threadIdx.x;
    if (i < N_NODES) { g_deg[i] = 1; g_fill[i] = 0; }  // deg=1: self loop pre-counted
    if (i < CPH) g_y[i] = 0.f;
}

// ---------------- K1: GEMM xh = x @ lin_w^T ----------------
// 64x64 tile, BK=16, 256 threads, 4x4 per thread.
// Smem stored k-major (transposed) so fragments load as LDS.128;
// inner product uses packed fma.rn.f32x2 (2 fp32 FMA per issue slot).
__global__ __launch_bounds__(256) void k_gemm(const float* __restrict__ x,
                                              const float* __restrict__ w) {
    __shared__ __align__(16) float As[16 * 68];   // [k][m], stride 68
    __shared__ __align__(16) float Bs[16 * 68];   // [k][n]
    int tid = threadIdx.x;
    int tx = tid & 15, ty = tid >> 4;
    int m0 = blockIdx.x * 64;
    int n0 = blockIdx.y * 64;

    unsigned long long acc2[4][2];
#pragma unroll
    for (int i = 0; i < 4; i++) { acc2[i][0] = 0ull; acc2[i][1] = 0ull; }

    int lrow = tid >> 2;            // 0..63 (m or n within tile)
    int lcol = (tid & 3) * 4;       // k sub-offset 0,4,8,12

    for (int k0 = 0; k0 < IN_CH; k0 += 16) {
        float4 av = *(const float4*)&x[(size_t)(m0 + lrow) * IN_CH + k0 + lcol];
        float4 bv = *(const float4*)&w[(size_t)(n0 + lrow) * IN_CH + k0 + lcol];
        As[(lcol + 0) * 68 + lrow] = av.x; As[(lcol + 1) * 68 + lrow] = av.y;
        As[(lcol + 2) * 68 + lrow] = av.z; As[(lcol + 3) * 68 + lrow] = av.w;
        Bs[(lcol + 0) * 68 + lrow] = bv.x; Bs[(lcol + 1) * 68 + lrow] = bv.y;
        Bs[(lcol + 2) * 68 + lrow] = bv.z; Bs[(lcol + 3) * 68 + lrow] = bv.w;
        __syncthreads();
#pragma unroll
        for (int k = 0; k < 16; k++) {
            float4 a4 = *(const float4*)&As[k * 68 + ty * 4];
            float4 b4 = *(const float4*)&Bs[k * 68 + tx * 4];
            unsigned long long b2lo = pk2(b4.x, b4.y);
            unsigned long long b2hi = pk2(b4.z, b4.w);
            unsigned long long a0 = pk2(a4.x, a4.x);
            unsigned long long a1 = pk2(a4.y, a4.y);
            unsigned long long a2 = pk2(a4.z, a4.z);
            unsigned long long a3 = pk2(a4.w, a4.w);
            fma2(acc2[0][0], a0, b2lo); fma2(acc2[0][1], a0, b2hi);
            fma2(acc2[1][0], a1, b2lo); fma2(acc2[1][1], a1, b2hi);
            fma2(acc2[2][0], a2, b2lo); fma2(acc2[2][1], a2, b2hi);
            fma2(acc2[3][0], a3, b2lo); fma2(acc2[3][1], a3, b2hi);
        }
        __syncthreads();
    }
#pragma unroll
    for (int i = 0; i < 4; i++) {
        float4 o;
        upk2(acc2[i][0], o.x, o.y);
        upk2(acc2[i][1], o.z, o.w);
        *(float4*)&g_xh[(size_t)(m0 + ty * 4 + i) * HC + n0 + tx * 4] = o;
    }
}

// ---------------- K2: per-node attention scalars ----------------
__global__ __launch_bounds__(256) void k_attvec(const float* __restrict__ att_src,
                                                const float* __restrict__ att_dst) {
    int n = blockIdx.x;
    int h = threadIdx.x >> 5;
    int c = threadIdx.x & 31;
    float v = g_xh[(size_t)n * HC + h * CPH + c];
    float s1 = v * att_src[h * CPH + c];
    float s2 = v * att_dst[h * CPH + c];
#pragma unroll
    for (int off = 16; off; off >>= 1) {
        s1 += __shfl_down_sync(0xffffffffu, s1, off);
        s2 += __shfl_down_sync(0xffffffffu, s2, off);
    }
    if (c == 0) { g_asrc[n * HEADS + h] = s1; g_adst[n * HEADS + h] = s2; }
}

// ---------------- K3a: degree histogram (int4 vectorized, self loops pre-counted) ----------------
__global__ void k_degree(const int* __restrict__ ei) {
    int t = blockIdx.x * blockDim.x + threadIdx.x;   // E_EDGES/4 threads
    int4 d = *(const int4*)&ei[E_EDGES + t * 4];
    atomicAdd(&g_deg[d.x], 1);
    atomicAdd(&g_deg[d.y], 1);
    atomicAdd(&g_deg[d.z], 1);
    atomicAdd(&g_deg[d.w], 1);
}

// ---------------- K3b: exclusive scan (single block, 1024 thr x 8) ----------------
__global__ __launch_bounds__(1024) void k_scan() {
    __shared__ int sh[1024];
    int t = threadIdx.x;
    int loc[8];
    int s = 0;
#pragma unroll
    for (int i = 0; i < 8; i++) { loc[i] = s; s += g_deg[t * 8 + i]; }
    sh[t] = s;
    __syncthreads();
    for (int off = 1; off < 1024; off <<= 1) {
        int v = (t >= off) ? sh[t - off] : 0;
        __syncthreads();
        sh[t] += v;
        __syncthreads();
    }
    int base = (t == 0) ? 0 : sh[t - 1];
#pragma unroll
    for (int i = 0; i < 8; i++) g_rowptr[t * 8 + i] = base + loc[i];
    if (t == 1023) g_rowptr[N_NODES] = sh[1023];
}

// ---------------- K3c: scatter src ids into CSR (vectorized + self loops) ----------------
#define SCAT_EDGE_BLOCKS (E_EDGES / 4 / 256)   // 256
__global__ void k_scatter(const int* __restrict__ ei) {
    if (blockIdx.x < SCAT_EDGE_BLOCKS) {
        int t = blockIdx.x * blockDim.x + threadIdx.x;
        int4 sv = *(const int4*)&ei[t * 4];
        int4 dv = *(const int4*)&ei[E_EDGES + t * 4];
        g_csrc[g_rowptr[dv.x] + atomicAdd(&g_fill[dv.x], 1)] = sv.x;
        g_csrc[g_rowptr[dv.y] + atomicAdd(&g_fill[dv.y], 1)] = sv.y;
        g_csrc[g_rowptr[dv.z] + atomicAdd(&g_fill[dv.z], 1)] = sv.z;
        g_csrc[g_rowptr[dv.w] + atomicAdd(&g_fill[dv.w], 1)] = sv.w;
    } else {
        int i = (blockIdx.x - SCAT_EDGE_BLOCKS) * blockDim.x + threadIdx.x;
        if (i < N_NODES)
            g_csrc[g_rowptr[i] + atomicAdd(&g_fill[i], 1)] = i;   // self loop
    }
}

// ---------------- K4: fused softmax + weighted aggregation ----------------
// No max pass: logits are bounded (|e| ~ 4), so alpha = exp(e)/sum exp(e)
// directly. exp computed exactly ONCE per edge-head; denominator accumulated
// alongside the aggregation. One block (256 thr) per destination node.
__global__ __launch_bounds__(256) void k_agg(const float* __restrict__ bias) {
    int i = blockIdx.x;
    int beg = g_rowptr[i], end = g_rowptr[i + 1];
    int tid = threadIdx.x;
    int h = tid >> 5;   // head of my channel

    __shared__ float s_adst[HEADS];
    __shared__ float s_alpha[32][9];     // stride 9: conflict-free stores
    __shared__ int   s_j[32];
    __shared__ float s_dinv[HEADS];
    if (tid < HEADS) s_adst[tid] = g_adst[i * HEADS + tid];

    float acc = 0.f;
    float ds[HEADS];                     // denominator partials (warp 0 only)
#pragma unroll
    for (int h2 = 0; h2 < HEADS; h2++) ds[h2] = 0.f;

    __syncthreads();
    for (int base = beg; base < end; base += 32) {
        int nn = min(32, end - base);
        if (tid < nn) {
            int j = g_csrc[base + tid];
            s_j[tid] = j;
#pragma unroll
            for (int h2 = 0; h2 < HEADS; h2++) {
                float v = g_asrc[j * HEADS + h2] + s_adst[h2];
                v = v > 0.f ? v : NEG_SLOPE * v;
                float ex = __expf(v);
                s_alpha[tid][h2] = ex;
                ds[h2] += ex;
            }
        }
        __syncthreads();
        for (int e = 0; e < nn; e++)
            acc = fmaf(s_alpha[e][h], g_xh[(size_t)s_j[e] * HC + tid], acc);
        __syncthreads();
    }
    // reduce denominator over warp 0 (cheap: adds + shuffles only)
    if (tid < 32) {
#pragma unroll
        for (int h2 = 0; h2 < HEADS; h2++) {
            float d = ds[h2];
#pragma unroll
            for (int off = 16; off; off >>= 1)
                d += __shfl_down_sync(0xffffffffu, d, off);
            if (tid == 0) s_dinv[h2] = 1.f / d;
        }
    }
    __syncthreads();
    g_v[(size_t)i * HC + tid] = fmaf(acc, s_dinv[h], bias[tid]);
}

// ---------------- K5: y[c] = sum_k v[k] * out_w[c,k] ----------------
#define CHUNK 4096
__global__ __launch_bounds__(256) void k_matvec(const float* __restrict__ out_w) {
    __shared__ float sv[CHUNK];
    __shared__ float s_part[CPH][8];
    int k0 = blockIdx.x * CHUNK;
    int tid = threadIdx.x;
    int lane = tid & 31, wid = tid >> 5;
    const float4* v4 = (const float4*)&g_v[k0];
    float4* sv4 = (float4*)sv;
    for (int i = tid; i < CHUNK / 4; i += 256) sv4[i] = v4[i];
    __syncthreads();
    for (int c = 0; c < CPH; c++) {
        const float4* w4 = (const float4*)(out_w + (size_t)c * VLEN + k0);
        float p = 0.f;
#pragma unroll
        for (int i = 0; i < CHUNK / 4 / 256; i++) {   // 4 independent float4 loads
            float4 wv = w4[tid + i * 256];
            float4 vv = sv4[tid + i * 256];
            p = fmaf(wv.x, vv.x, p);
            p = fmaf(wv.y, vv.y, p);
            p = fmaf(wv.z, vv.z, p);
            p = fmaf(wv.w, vv.w, p);
        }
#pragma unroll
        for (int off = 16; off; off >>= 1) p += __shfl_down_sync(0xffffffffu, p, off);
        if (lane == 0) s_part[c][wid] = p;
    }
    __syncthreads();
    if (tid < CPH) {
        float t = 0.f;
#pragma unroll
        for (int w = 0; w < 8; w++) t += s_part[tid][w];
        atomicAdd(&g_y[tid], t);
    }
}

// ---------------- K6: softmax over 32 logits ----------------
__global__ void k_softmax(const float* __restrict__ out_b, float* __restrict__ out) {
    int t = threadIdx.x;  // 32 threads
    float v = g_y[t] + out_b[t];
    float mx = v;
#pragma unroll
    for (int off = 16; off; off >>= 1) mx = fmaxf(mx, __shfl_xor_sync(0xffffffffu, mx, off));
    float e = expf(v - mx);
    float ssum = e;
#pragma unroll
    for (int off = 16; off; off >>= 1) ssum += __shfl_xor_sync(0xffffffffu, ssum, off);
    out[t] = e / ssum;
}

// ---------------- launch ----------------
extern "C" void kernel_launch(void* const* d_in, const int* in_sizes, int n_in,
                              void* d_out, int out_size) {
    const float* x       = (const float*)d_in[0];
    const int*   ei      = (const int*)d_in[1];
    const float* lin_w   = (const float*)d_in[2];
    const float* att_src = (const float*)d_in[3];
    const float* att_dst = (const float*)d_in[4];
    const float* bias    = (const float*)d_in[5];
    const float* out_w   = (const float*)d_in[6];
    const float* out_b   = (const float*)d_in[7];
    float* out = (float*)d_out;

    k_zero<<<(N_NODES + 255) / 256, 256>>>();
    k_gemm<<<dim3(N_NODES / 64, HC / 64), 256>>>(x, lin_w);
    k_attvec<<<N_NODES, 256>>>(att_src, att_dst);
    k_degree<<<E_EDGES / 4 / 256, 256>>>(ei);
    k_scan<<<1, 1024>>>();
    k_scatter<<<SCAT_EDGE_BLOCKS + (N_NODES + 255) / 256, 256>>>(ei);
    k_agg<<<N_NODES, 256>>>(bias);
    k_matvec<<<VLEN / CHUNK, 256>>>(out_w);
    k_softmax<<<1, 32>>>(out_b, out);
}

// round 7
// speedup vs baseline: 1.6623x; 1.0783x over previous
#include <cuda_runtime.h>
#include <math.h>

#define N_NODES 8192
#define E_EDGES 262144
#define E_TOT   (E_EDGES + N_NODES)   // 270336, with self loops
#define IN_CH   256
#define HEADS   8
#define CPH     32
#define HC      256                    // HEADS*CPH
#define VLEN    (N_NODES * HC)         // 2097152
#define NEG_SLOPE 0.2f

// ---------------- device scratch (no allocations allowed) ----------------
__device__ float g_xh[N_NODES * HC];        // projected features [n, h*c]
__device__ float g_asrc[N_NODES * HEADS];
__device__ float g_adst[N_NODES * HEADS];
__device__ int   g_deg[N_NODES];
__device__ int   g_fill[N_NODES];
__device__ int   g_rowptr[N_NODES + 1];
__device__ int   g_csrc[E_TOT];
__device__ float g_v[VLEN];                 // agg + bias, flattened
__device__ float g_y[CPH];                  // partial output logits

// ---------------- packed f32x2 helpers (Blackwell FFMA2) ----------------
__device__ __forceinline__ unsigned long long pk2(float lo, float hi) {
    unsigned long long r;
    asm("mov.b64 %0, {%1, %2};" : "=l"(r) : "f"(lo), "f"(hi));
    return r;
}
__device__ __forceinline__ void upk2(unsigned long long v, float& lo, float& hi) {
    asm("mov.b64 {%0, %1}, %2;" : "=f"(lo), "=f"(hi) : "l"(v));
}
__device__ __forceinline__ void fma2(unsigned long long& d,
                                     unsigned long long a, unsigned long long b) {
    asm("fma.rn.f32x2 %0, %1, %2, %3;" : "=l"(d) : "l"(a), "l"(b), "l"(d));
}

// ---------------- K0: init scratch ----------------
__global__ void k_zero() {
    int i = blockIdx.x * blockDim.x + threadIdx.x;
    if (i < N_NODES) { g_deg[i] = 1; g_fill[i] = 0; }  // deg=1: self loop pre-counted
    if (i < CPH) g_y[i] = 0.f;
}

// ---------------- K1: GEMM xh = x @ lin_w^T ----------------
// 64x64 tile, BK=16, 256 threads, 4x4 per thread, k-major smem, FFMA2 core.
__global__ __launch_bounds__(256) void k_gemm(const float* __restrict__ x,
                                              const float* __restrict__ w) {
    __shared__ __align__(16) float As[16 * 68];   // [k][m], stride 68
    __shared__ __align__(16) float Bs[16 * 68];   // [k][n]
    int tid = threadIdx.x;
    int tx = tid & 15, ty = tid >> 4;
    int m0 = blockIdx.x * 64;
    int n0 = blockIdx.y * 64;

    unsigned long long acc2[4][2];
#pragma unroll
    for (int i = 0; i < 4; i++) { acc2[i][0] = 0ull; acc2[i][1] = 0ull; }

    int lrow = tid >> 2;            // 0..63 (m or n within tile)
    int lcol = (tid & 3) * 4;       // k sub-offset 0,4,8,12

    for (int k0 = 0; k0 < IN_CH; k0 += 16) {
        float4 av = *(const float4*)&x[(size_t)(m0 + lrow) * IN_CH + k0 + lcol];
        float4 bv = *(const float4*)&w[(size_t)(n0 + lrow) * IN_CH + k0 + lcol];
        As[(lcol + 0) * 68 + lrow] = av.x; As[(lcol + 1) * 68 + lrow] = av.y;
        As[(lcol + 2) * 68 + lrow] = av.z; As[(lcol + 3) * 68 + lrow] = av.w;
        Bs[(lcol + 0) * 68 + lrow] = bv.x; Bs[(lcol + 1) * 68 + lrow] = bv.y;
        Bs[(lcol + 2) * 68 + lrow] = bv.z; Bs[(lcol + 3) * 68 + lrow] = bv.w;
        __syncthreads();
#pragma unroll
        for (int k = 0; k < 16; k++) {
            float4 a4 = *(const float4*)&As[k * 68 + ty * 4];
            float4 b4 = *(const float4*)&Bs[k * 68 + tx * 4];
            unsigned long long b2lo = pk2(b4.x, b4.y);
            unsigned long long b2hi = pk2(b4.z, b4.w);
            unsigned long long a0 = pk2(a4.x, a4.x);
            unsigned long long a1 = pk2(a4.y, a4.y);
            unsigned long long a2 = pk2(a4.z, a4.z);
            unsigned long long a3 = pk2(a4.w, a4.w);
            fma2(acc2[0][0], a0, b2lo); fma2(acc2[0][1], a0, b2hi);
            fma2(acc2[1][0], a1, b2lo); fma2(acc2[1][1], a1, b2hi);
            fma2(acc2[2][0], a2, b2lo); fma2(acc2[2][1], a2, b2hi);
            fma2(acc2[3][0], a3, b2lo); fma2(acc2[3][1], a3, b2hi);
        }
        __syncthreads();
    }
#pragma unroll
    for (int i = 0; i < 4; i++) {
        float4 o;
        upk2(acc2[i][0], o.x, o.y);
        upk2(acc2[i][1], o.z, o.w);
        *(float4*)&g_xh[(size_t)(m0 + ty * 4 + i) * HC + n0 + tx * 4] = o;
    }
}

// ---------------- K2: per-node attention scalars ----------------
__global__ __launch_bounds__(256) void k_attvec(const float* __restrict__ att_src,
                                                const float* __restrict__ att_dst) {
    int n = blockIdx.x;
    int h = threadIdx.x >> 5;
    int c = threadIdx.x & 31;
    float v = g_xh[(size_t)n * HC + h * CPH + c];
    float s1 = v * att_src[h * CPH + c];
    float s2 = v * att_dst[h * CPH + c];
#pragma unroll
    for (int off = 16; off; off >>= 1) {
        s1 += __shfl_down_sync(0xffffffffu, s1, off);
        s2 += __shfl_down_sync(0xffffffffu, s2, off);
    }
    if (c == 0) { g_asrc[n * HEADS + h] = s1; g_adst[n * HEADS + h] = s2; }
}

// ---------------- K3a: degree histogram (1 edge/thread, fire-and-forget RED) ----------------
__global__ void k_degree(const int* __restrict__ ei) {
    int e = blockIdx.x * blockDim.x + threadIdx.x;   // E_EDGES threads
    atomicAdd(&g_deg[ei[E_EDGES + e]], 1);
}

// ---------------- K3b: exclusive scan (single block, 1024 thr x 8) ----------------
__global__ __launch_bounds__(1024) void k_scan() {
    __shared__ int sh[1024];
    int t = threadIdx.x;
    int loc[8];
    int s = 0;
#pragma unroll
    for (int i = 0; i < 8; i++) { loc[i] = s; s += g_deg[t * 8 + i]; }
    sh[t] = s;
    __syncthreads();
    for (int off = 1; off < 1024; off <<= 1) {
        int v = (t >= off) ? sh[t - off] : 0;
        __syncthreads();
        sh[t] += v;
        __syncthreads();
    }
    int base = (t == 0) ? 0 : sh[t - 1];
#pragma unroll
    for (int i = 0; i < 8; i++) g_rowptr[t * 8 + i] = base + loc[i];
    if (t == 1023) g_rowptr[N_NODES] = sh[1023];
}

// ---------------- K3c: scatter src ids into CSR (vectorized + self loops) ----------------
#define SCAT_EDGE_BLOCKS (E_EDGES / 4 / 256)   // 256
__global__ void k_scatter(const int* __restrict__ ei) {
    if (blockIdx.x < SCAT_EDGE_BLOCKS) {
        int t = blockIdx.x * blockDim.x + threadIdx.x;
        int4 sv = *(const int4*)&ei[t * 4];
        int4 dv = *(const int4*)&ei[E_EDGES + t * 4];
        g_csrc[g_rowptr[dv.x] + atomicAdd(&g_fill[dv.x], 1)] = sv.x;
        g_csrc[g_rowptr[dv.y] + atomicAdd(&g_fill[dv.y], 1)] = sv.y;
        g_csrc[g_rowptr[dv.z] + atomicAdd(&g_fill[dv.z], 1)] = sv.z;
        g_csrc[g_rowptr[dv.w] + atomicAdd(&g_fill[dv.w], 1)] = sv.w;
    } else {
        int i = (blockIdx.x - SCAT_EDGE_BLOCKS) * blockDim.x + threadIdx.x;
        if (i < N_NODES)
            g_csrc[g_rowptr[i] + atomicAdd(&g_fill[i], 1)] = i;   // self loop
    }
}

// ---------------- K4: fused softmax + aggregation, warp-per-(node,head) ----------------
// Block i, warp h handles head h of node i. Each lane computes the alpha of
// its own edge (one __expf), the denominator is accumulated lane-parallel,
// and the weighted gather uses shuffle broadcast. No smem, no __syncthreads.
__global__ __launch_bounds__(256) void k_agg(const float* __restrict__ bias) {
    int i = blockIdx.x;
    int lane = threadIdx.x & 31;
    int h = threadIdx.x >> 5;
    int beg = g_rowptr[i], end = g_rowptr[i + 1];

    float adst_h = g_adst[i * HEADS + h];
    float acc = 0.f, ds = 0.f;

    for (int base = beg; base < end; base += 32) {
        int e = base + lane;
        int j = 0;
        float alpha = 0.f;
        if (e < end) {
            j = g_csrc[e];
            float v = g_asrc[j * HEADS + h] + adst_h;
            v = v > 0.f ? v : NEG_SLOPE * v;
            alpha = __expf(v);
            ds += alpha;
        }
        int nn = min(32, end - base);
        for (int t = 0; t < nn; t++) {
            float a = __shfl_sync(0xffffffffu, alpha, t);
            int jj  = __shfl_sync(0xffffffffu, j, t);
            acc = fmaf(a, g_xh[(size_t)jj * HC + h * CPH + lane], acc);
        }
    }
#pragma unroll
    for (int off = 16; off; off >>= 1)
        ds += __shfl_xor_sync(0xffffffffu, ds, off);
    float dinv = 1.f / ds;
    g_v[(size_t)i * HC + h * CPH + lane] = fmaf(acc, dinv, bias[h * CPH + lane]);
}

// ---------------- K5: y[c] = sum_k v[k] * out_w[c,k] ----------------
#define CHUNK 2048
__global__ __launch_bounds__(256) void k_matvec(const float* __restrict__ out_w) {
    __shared__ float sv[CHUNK];
    __shared__ float s_part[CPH][8];
    int k0 = blockIdx.x * CHUNK;
    int tid = threadIdx.x;
    int lane = tid & 31, wid = tid >> 5;
    const float4* v4 = (const float4*)&g_v[k0];
    float4* sv4 = (float4*)sv;
    for (int i = tid; i < CHUNK / 4; i += 256) sv4[i] = v4[i];
    __syncthreads();
    for (int c = 0; c < CPH; c++) {
        const float4* w4 = (const float4*)(out_w + (size_t)c * VLEN + k0);
        float p = 0.f;
#pragma unroll
        for (int i = 0; i < CHUNK / 4 / 256; i++) {
            float4 wv = w4[tid + i * 256];
            float4 vv = sv4[tid + i * 256];
            p = fmaf(wv.x, vv.x, p);
            p = fmaf(wv.y, vv.y, p);
            p = fmaf(wv.z, vv.z, p);
            p = fmaf(wv.w, vv.w, p);
        }
#pragma unroll
        for (int off = 16; off; off >>= 1) p += __shfl_down_sync(0xffffffffu, p, off);
        if (lane == 0) s_part[c][wid] = p;
    }
    __syncthreads();
    if (tid < CPH) {
        float t = 0.f;
#pragma unroll
        for (int w = 0; w < 8; w++) t += s_part[tid][w];
        atomicAdd(&g_y[tid], t);
    }
}

// ---------------- K6: softmax over 32 logits ----------------
__global__ void k_softmax(const float* __restrict__ out_b, float* __restrict__ out) {
    int t = threadIdx.x;  // 32 threads
    float v = g_y[t] + out_b[t];
    float mx = v;
#pragma unroll
    for (int off = 16; off; off >>= 1) mx = fmaxf(mx, __shfl_xor_sync(0xffffffffu, mx, off));
    float e = expf(v - mx);
    float ssum = e;
#pragma unroll
    for (int off = 16; off; off >>= 1) ssum += __shfl_xor_sync(0xffffffffu, ssum, off);
    out[t] = e / ssum;
}

// ---------------- launch ----------------
extern "C" void kernel_launch(void* const* d_in, const int* in_sizes, int n_in,
                              void* d_out, int out_size) {
    const float* x       = (const float*)d_in[0];
    const int*   ei      = (const int*)d_in[1];
    const float* lin_w   = (const float*)d_in[2];
    const float* att_src = (const float*)d_in[3];
    const float* att_dst = (const float*)d_in[4];
    const float* bias    = (const float*)d_in[5];
    const float* out_w   = (const float*)d_in[6];
    const float* out_b   = (const float*)d_in[7];
    float* out = (float*)d_out;

    k_zero<<<(N_NODES + 255) / 256, 256>>>();
    k_gemm<<<dim3(N_NODES / 64, HC / 64), 256>>>(x, lin_w);
    k_attvec<<<N_NODES, 256>>>(att_src, att_dst);
    k_degree<<<E_EDGES / 256, 256>>>(ei);
    k_scan<<<1, 1024>>>();
    k_scatter<<<SCAT_EDGE_BLOCKS + (N_NODES + 255) / 256, 256>>>(ei);
    k_agg<<<N_NODES, 256>>>(bias);
    k_matvec<<<VLEN / CHUNK, 256>>>(out_w);
    k_softmax<<<1, 32>>>(out_b, out);
}